// round 11
// baseline (speedup 1.0000x reference)
#include <cuda_runtime.h>
#include <cuda_fp16.h>
#include <cuda_bf16.h>
#include <math.h>
#include <stdint.h>

#define LNF 128      // feat dim
#define SS  32       // stat dim
#define CC  10       // classes
#define NPQ 2048     // GEMM N: P(1024) || Q(1024)
#define MAXV 50000
#define MAXE 200000
#define MU_OVER_S (0.9f / 32.0f)
#define SCAN_BLK 512
#define MAXB ((MAXV + SCAN_BLK - 1) / SCAN_BLK)   // 98
#define WSCALE 64.0f
#define INV_WSCALE (1.0f / 64.0f)

// -------- static device scratch --------
__device__ __half         g_Ph[(size_t)MAXV * 1024];   // fp16 P (bxi folded), 102 MB
__device__ uint8_t        g_Qf8[(size_t)MAXV * 1024];  // e4m3 Q, 51 MB (L2-resident)
__device__ uint8_t        g_W2q[NPQ * LNF];            // e4m3 W2 * 64, K-major [2048][128]
__device__ uint8_t        g_fa[(size_t)MAXV * LNF];    // e4m3 feat [V][128]
__device__ float          g_R[MAXV * SS];              // fp32 R
__device__ float          g_hacc[MAXV * SS];
__device__ int            g_cnt[MAXV];
__device__ int            g_fill[MAXV];
__device__ int            g_off[MAXV + 1];
__device__ int            g_bsum[MAXB];
__device__ int            g_ev[MAXE];
__device__ float          g_esc[MAXE];

__device__ __forceinline__ __half2 h2tanh_fast(__half2 x) {
    uint32_t xi = *(uint32_t*)&x, yi;
    asm("tanh.approx.f16x2 %0, %1;" : "=r"(yi) : "r"(xi));
    return *(__half2*)&yi;
}
__device__ __forceinline__ __half2 e4m3x2_to_h2(uint16_t x) {
    uint32_t r;
    asm("cvt.rn.f16x2.e4m3x2 %0, %1;" : "=r"(r) : "h"(x));
    return *(__half2*)&r;
}
// pack (v0 -> low byte, v1 -> high byte)
__device__ __forceinline__ uint16_t f32x2_to_e4m3x2(float v0, float v1) {
    uint16_t r;
    asm("cvt.rn.satfinite.e4m3x2.f32 %0, %1, %2;" : "=h"(r) : "f"(v1), "f"(v0));
    return r;
}

// ---------------- pack W2 (K-major fp8, scaled by 64) + cnt zero ----------------
__global__ void pack_w2_kernel(const float* __restrict__ Wxi, int V) {
    int idx = blockIdx.x * blockDim.x + threadIdx.x;   // over byte pairs
    if (idx < V) g_cnt[idx] = 0;
    if (idx >= NPQ * LNF / 2) return;
    int n = idx / (LNF / 2);
    int k = (idx - n * (LNF / 2)) * 2;
    float v0, v1;
    if (n < 1024) {
        v0 = Wxi[(size_t)k * 1024 + n];
        v1 = Wxi[(size_t)(k + 1) * 1024 + n];
    } else {
        v0 = Wxi[(size_t)(k + LNF) * 1024 + (n - 1024)];
        v1 = Wxi[(size_t)(k + 1 + LNF) * 1024 + (n - 1024)];
    }
    *(uint16_t*)(g_W2q + (size_t)n * LNF + k) = f32x2_to_e4m3x2(v0 * WSCALE, v1 * WSCALE);
}

// ---------------- CSR build ----------------
__global__ void count_kernel(const int* __restrict__ Xn, int E) {
    int e = blockIdx.x * blockDim.x + threadIdx.x;
    if (e < E) atomicAdd(&g_cnt[Xn[e]], 1);
}

__global__ __launch_bounds__(SCAN_BLK) void scan1_kernel(int V) {
    __shared__ int s[SCAN_BLK];
    int i = blockIdx.x * SCAN_BLK + threadIdx.x;
    s[threadIdx.x] = (i < V) ? g_cnt[i] : 0;
    __syncthreads();
#pragma unroll
    for (int off = SCAN_BLK / 2; off > 0; off >>= 1) {
        if (threadIdx.x < off) s[threadIdx.x] += s[threadIdx.x + off];
        __syncthreads();
    }
    if (threadIdx.x == 0) g_bsum[blockIdx.x] = s[0];
}

__global__ __launch_bounds__(128) void scan2_kernel(int nb, int V) {
    __shared__ int s[128];
    int t = threadIdx.x;
    int v = (t < nb) ? g_bsum[t] : 0;
    s[t] = v;
    __syncthreads();
#pragma unroll
    for (int off = 1; off < 128; off <<= 1) {
        int x = (t >= off) ? s[t - off] : 0;
        __syncthreads();
        s[t] += x;
        __syncthreads();
    }
    if (t < nb) g_bsum[t] = s[t] - v;        // exclusive
    if (t == 127) g_off[V] = s[127];          // total
}

__global__ __launch_bounds__(SCAN_BLK) void scan3_kernel(int V) {
    __shared__ int s[SCAN_BLK];
    int i = blockIdx.x * SCAN_BLK + threadIdx.x;
    int v = (i < V) ? g_cnt[i] : 0;
    s[threadIdx.x] = v;
    __syncthreads();
#pragma unroll
    for (int off = 1; off < SCAN_BLK; off <<= 1) {
        int x = (threadIdx.x >= off) ? s[threadIdx.x - off] : 0;
        __syncthreads();
        s[threadIdx.x] += x;
        __syncthreads();
    }
    if (i < V) {
        g_off[i]  = g_bsum[blockIdx.x] + s[threadIdx.x] - v;   // exclusive
        g_fill[i] = 0;
    }
}

__global__ void fill_kernel(const int* __restrict__ Xn, const int* __restrict__ Xe,
                            const float* __restrict__ dg, int E) {
    int e = blockIdx.x * blockDim.x + threadIdx.x;
    if (e >= E) return;
    int u = Xn[e];
    int pos = g_off[u] + atomicAdd(&g_fill[u], 1);
    g_ev[pos]  = Xe[e];
    g_esc[pos] = MU_OVER_S / dg[e];
}

// ---------------- fp8 MMA GEMM: PQ[M x 2048] = feat_e4m3[M x 128] @ (W2*64)_e4m3 ----------------
// Block tile 128(M) x 128(N), full K staged once; 8 warps = 4(M) x 2(N), warp 32x64.
// 4 k-steps of k32; per warp per k-step: 2 ldsm(A) + 4 ldsm(B) + 16 mma.
#define TROW 144                            // smem row stride in bytes (128 data + 16 pad)
#define SMEM_Bq_OFF (128 * TROW)            // bytes
#define GEMM_SMEM_BYTES (2 * 128 * TROW)    // 36864 B

__device__ __forceinline__ void ldsm_x4(uint32_t& r0, uint32_t& r1, uint32_t& r2, uint32_t& r3,
                                        uint32_t addr) {
    asm volatile("ldmatrix.sync.aligned.m8n8.x4.shared.b16 {%0,%1,%2,%3}, [%4];"
                 : "=r"(r0), "=r"(r1), "=r"(r2), "=r"(r3) : "r"(addr));
}
__device__ __forceinline__ void mma_fp8(float* c, const uint32_t* a, uint32_t b0, uint32_t b1) {
    asm volatile(
        "mma.sync.aligned.m16n8k32.row.col.f32.e4m3.e4m3.f32 "
        "{%0,%1,%2,%3}, {%4,%5,%6,%7}, {%8,%9}, {%0,%1,%2,%3};\n"
        : "+f"(c[0]), "+f"(c[1]), "+f"(c[2]), "+f"(c[3])
        : "r"(a[0]), "r"(a[1]), "r"(a[2]), "r"(a[3]), "r"(b0), "r"(b1));
}
__device__ __forceinline__ void cp_async16(uint32_t saddr, const void* gaddr) {
    asm volatile("cp.async.cg.shared.global [%0], [%1], 16;" :: "r"(saddr), "l"(gaddr));
}

__device__ __forceinline__ void epi_store_pair(int row, int c, float v0, float v1, int M,
                                               const float* __restrict__ bxi) {
    if (row >= M) return;
    v0 *= INV_WSCALE;
    v1 *= INV_WSCALE;
    if (c < 1024) {
        v0 += __ldg(&bxi[c]);
        v1 += __ldg(&bxi[c + 1]);
        __stcs((__half2*)(g_Ph + (size_t)row * 1024 + c), __floats2half2_rn(v0, v1));
    } else {
        int qc = c - 1024;
        *(uint16_t*)(g_Qf8 + (size_t)row * 1024 + qc) = f32x2_to_e4m3x2(v0, v1);
    }
}

__global__ __launch_bounds__(256) void gemm_fp8_kernel(const float* __restrict__ bxi, int M) {
    extern __shared__ uint8_t smem[];

    const int tid  = threadIdx.x;
    const int warp = tid >> 5;
    const int lane = tid & 31;
    const int g    = lane >> 2;
    const int t4   = lane & 3;
    const int wm   = warp & 3;       // 0..3 over M (32 rows each)
    const int wn   = warp >> 2;      // 0..1 over N (64 cols each)
    const int row0 = blockIdx.y * 128;
    const int col0 = blockIdx.x * 128;

    uint32_t smem_base;
    asm("{ .reg .u64 t; cvta.to.shared.u64 t, %1; cvt.u32.u64 %0, t; }"
        : "=r"(smem_base) : "l"(smem));
    const uint32_t b_base = smem_base + SMEM_Bq_OFF;

    // Stage A (feat fp8) and B (W2q fp8): each 128 rows x 8 segs of 16B = 1024 chunks, 4/thread.
#pragma unroll
    for (int i = 0; i < 4; ++i) {
        int c = tid + i * 256;
        int r = c >> 3;               // row 0..127
        int seg = c & 7;              // 16B segment
        int grow = row0 + r; if (grow >= M) grow = M - 1;
        cp_async16(smem_base + (uint32_t)(r * TROW + seg * 16),
                   g_fa + (size_t)grow * LNF + seg * 16);
        cp_async16(b_base + (uint32_t)(r * TROW + seg * 16),
                   g_W2q + (size_t)(col0 + r) * LNF + seg * 16);
    }
    asm volatile("cp.async.commit_group;");
    asm volatile("cp.async.wait_group 0;");
    __syncthreads();

    float acc[2][8][4];
#pragma unroll
    for (int mt = 0; mt < 2; ++mt)
#pragma unroll
        for (int nt = 0; nt < 8; ++nt)
#pragma unroll
            for (int r = 0; r < 4; ++r) acc[mt][nt][r] = 0.0f;

#pragma unroll
    for (int ks = 0; ks < 4; ++ks) {
        const int kb = ks * 32;                 // byte offset in K
        uint32_t a[2][4];
        // A frags: matrices (rows ar..+7, kb..+15),(ar+8..+15, kb..+15),(ar.., kb+16..),(ar+8, kb+16..)
#pragma unroll
        for (int mt = 0; mt < 2; ++mt) {
            int ar = wm * 32 + mt * 16;
            uint32_t addr = smem_base +
                (uint32_t)((ar + (lane & 15)) * TROW + kb + ((lane >> 4) << 4));
            ldsm_x4(a[mt][0], a[mt][1], a[mt][2], a[mt][3], addr);
        }
        // B frags: per n16 group: m0=(n..+7,kb..15) m1=(n..+7,kb+16..) m2=(n+8..,kb..) m3=(n+8..,kb+16)
#pragma unroll
        for (int np = 0; np < 4; ++np) {
            int nc = wn * 64 + np * 16;
            int brow = nc + (lane & 7) + ((lane >> 4) << 3);
            int bbyte = kb + (((lane >> 3) & 1) << 4);
            uint32_t b0, b1, b2, b3;
            uint32_t addr = b_base + (uint32_t)(brow * TROW + bbyte);
            ldsm_x4(b0, b1, b2, b3, addr);
#pragma unroll
            for (int mt = 0; mt < 2; ++mt) {
                mma_fp8(acc[mt][np * 2],     a[mt], b0, b1);
                mma_fp8(acc[mt][np * 2 + 1], a[mt], b2, b3);
            }
        }
    }

    // epilogue: scale 1/64, add bxi (cols < 1024) -> fp16 P; cols >= 1024 -> fp8 Q
#pragma unroll
    for (int mt = 0; mt < 2; ++mt) {
        int rlo = row0 + wm * 32 + mt * 16 + g;
#pragma unroll
        for (int nt = 0; nt < 8; ++nt) {
            int c = col0 + wn * 64 + nt * 8 + 2 * t4;
            epi_store_pair(rlo,     c, acc[mt][nt][0], acc[mt][nt][1], M, bxi);
            epi_store_pair(rlo + 8, c, acc[mt][nt][2], acc[mt][nt][3], M, bxi);
        }
    }
}

// ---------------- R kernel (fp32) + fused feat->e4m3 conversion ----------------
#define RNODES 48
__global__ __launch_bounds__(256) void r_kernel(const float* __restrict__ feat,
                                                const float* __restrict__ Wrou,
                                                const float* __restrict__ brou, int V) {
    __shared__ float Ws[LNF * SS];
    __shared__ float fr[RNODES * LNF];
    const int tid = threadIdx.x;
    const int n0 = blockIdx.x * RNODES;

    for (int i = tid; i < LNF * SS; i += 256) Ws[i] = Wrou[i];
    for (int i = tid; i < RNODES * LNF / 4; i += 256) {
        int node = n0 + (i * 4) / LNF;
        if (node >= V) node = V - 1;
        int k = (i * 4) & (LNF - 1);
        *(float4*)&fr[i * 4] = *(const float4*)(feat + (size_t)node * LNF + k);
    }
    __syncthreads();

    // fused e4m3 conversion (g_fa feeds the fp8 GEMM)
    for (int i = tid; i < RNODES * LNF / 2; i += 256) {
        int node = n0 + (i * 2) / LNF;
        if (node < V) {
            int k = (i * 2) & (LNF - 1);
            *(uint16_t*)(g_fa + (size_t)node * LNF + k) =
                f32x2_to_e4m3x2(fr[i * 2], fr[i * 2 + 1]);
        }
    }

    const int warp = tid >> 5, lane = tid & 31;
    float acc[6];
#pragma unroll
    for (int i = 0; i < 6; ++i) acc[i] = 0.0f;
    const float* fbase = &fr[warp * 6 * LNF];
#pragma unroll 16
    for (int k = 0; k < LNF; ++k) {
        float wv = Ws[k * SS + lane];
#pragma unroll
        for (int i = 0; i < 6; ++i) acc[i] = fmaf(fbase[i * LNF + k], wv, acc[i]);
    }
    float bb = brou[lane];
#pragma unroll
    for (int i = 0; i < 6; ++i) {
        int node = n0 + warp * 6 + i;
        if (node < V) g_R[node * SS + lane] = tanhf(acc[i] + bb);
    }
}

// ---------------- edge kernel: single pass, lane = output row, Q in fp8 ----------------
__global__ __launch_bounds__(256) void edge_kernel(int V) {
    __shared__ float rs[8][SS];
    const int warp = threadIdx.x >> 5;
    const int lane = threadIdx.x & 31;
    const int u = blockIdx.x * 8 + warp;
    if (u >= V) return;
    const int n = g_cnt[u];
    if (n == 0) return;
    const int start = g_off[u];

    rs[warp][lane] = g_R[u * SS + lane];
    __syncwarp();

    const uint4* Pp = (const uint4*)(g_Ph + (size_t)u * 1024 + lane * 32);
    uint4 pr[4] = {__ldcs(Pp), __ldcs(Pp + 1), __ldcs(Pp + 2), __ldcs(Pp + 3)};
    const __half2* ph = (const __half2*)pr;      // 16 half2

    float racc = 0.0f;
    for (int e = start; e < start + n; ++e) {
        const int v = g_ev[e];
        const float sc = g_esc[e];
        const uint4* qp = (const uint4*)(g_Qf8 + (size_t)v * 1024 + lane * 32);
        uint4 q0 = qp[0];
        uint4 q1 = qp[1];
        const uint16_t* qa = (const uint16_t*)&q0;
        const uint16_t* qb = (const uint16_t*)&q1;

        float partial = 0.0f;
#pragma unroll
        for (int k = 0; k < 8; ++k) {
            float2 t = __half22float2(h2tanh_fast(__hadd2(ph[k], e4m3x2_to_h2(qa[k]))));
            partial = fmaf(t.x, rs[warp][2 * k],     partial);
            partial = fmaf(t.y, rs[warp][2 * k + 1], partial);
        }
#pragma unroll
        for (int k = 0; k < 8; ++k) {
            float2 t = __half22float2(h2tanh_fast(__hadd2(ph[8 + k], e4m3x2_to_h2(qb[k]))));
            partial = fmaf(t.x, rs[warp][16 + 2 * k], partial);
            partial = fmaf(t.y, rs[warp][17 + 2 * k], partial);
        }
        racc = fmaf(partial, sc, racc);
    }
    g_hacc[u * SS + lane] = racc;
}

// ---------------- output ----------------
__global__ __launch_bounds__(256) void out_kernel(const float* __restrict__ Wout,
                                                  const float* __restrict__ bout,
                                                  float* __restrict__ out, int V) {
    int gtid = blockIdx.x * blockDim.x + threadIdx.x;
    int vtx = gtid >> 5;
    int lane = threadIdx.x & 31;
    if (vtx >= V) return;

    float c = (float)g_cnt[vtx];
    float Hf = (c > 0.0f) ? c * (g_hacc[vtx * SS + lane] + g_R[vtx * SS + lane]) : 0.0f;

    float mine = 0.0f;
    float logits[CC];
#pragma unroll
    for (int j = 0; j < CC; ++j) {
        float p = Hf * Wout[lane * CC + j];
#pragma unroll
        for (int off = 16; off > 0; off >>= 1)
            p += __shfl_xor_sync(0xffffffffu, p, off);
        logits[j] = p + bout[j];
        if (j == lane) mine = logits[j];
    }
    float m = logits[0];
#pragma unroll
    for (int j = 1; j < CC; ++j) m = fmaxf(m, logits[j]);
    float se = 0.0f;
#pragma unroll
    for (int j = 0; j < CC; ++j) se += expf(logits[j] - m);
    float lse = m + logf(se);

    if (lane < CC) out[(size_t)vtx * CC + lane] = mine - lse;
}

// ---------------- launch ----------------
extern "C" void kernel_launch(void* const* d_in, const int* in_sizes, int n_in,
                              void* d_out, int out_size) {
    const float* feat = (const float*)d_in[0];
    const int*   Xn   = (const int*)d_in[1];
    const int*   Xe   = (const int*)d_in[2];
    const float* dg   = (const float*)d_in[3];
    const float* Wxi  = (const float*)d_in[4];
    const float* bxi  = (const float*)d_in[5];
    const float* Wrou = (const float*)d_in[6];
    const float* brou = (const float*)d_in[7];
    const float* Wout = (const float*)d_in[8];
    const float* bout = (const float*)d_in[9];
    float* out = (float*)d_out;

    const int V = in_sizes[0] / LNF;
    const int E = in_sizes[1];
    const int nb = (V + SCAN_BLK - 1) / SCAN_BLK;

    cudaFuncSetAttribute(gemm_fp8_kernel,
                         cudaFuncAttributeMaxDynamicSharedMemorySize, GEMM_SMEM_BYTES);

    pack_w2_kernel<<<(NPQ * LNF / 2 + 255) / 256, 256>>>(Wxi, V);   // also zeroes g_cnt
    count_kernel<<<(E + 255) / 256, 256>>>(Xn, E);
    scan1_kernel<<<nb, SCAN_BLK>>>(V);
    scan2_kernel<<<1, 128>>>(nb, V);
    scan3_kernel<<<nb, SCAN_BLK>>>(V);
    fill_kernel<<<(E + 255) / 256, 256>>>(Xn, Xe, dg, E);

    r_kernel<<<(V + RNODES - 1) / RNODES, 256>>>(feat, Wrou, brou, V);   // also writes g_fa

    dim3 ggrid(NPQ / 128, (V + 127) / 128);
    gemm_fp8_kernel<<<ggrid, 256, GEMM_SMEM_BYTES>>>(bxi, V);

    edge_kernel<<<(V + 7) / 8, 256>>>(V);
    out_kernel<<<(V * 32 + 255) / 256, 256>>>(Wout, bout, out, V);
}

// round 12
// speedup vs baseline: 1.1861x; 1.1861x over previous
#include <cuda_runtime.h>
#include <cuda_fp16.h>
#include <cuda_bf16.h>
#include <math.h>
#include <stdint.h>

#define LNF 128      // feat dim
#define SS  32       // stat dim
#define CC  10       // classes
#define NPQ 2048     // GEMM N: P(1024) || Q(1024)
#define MAXV 50000
#define MAXE 200000
#define MU_OVER_S (0.9f / 32.0f)
#define SCAN_BLK 512
#define MAXB ((MAXV + SCAN_BLK - 1) / SCAN_BLK)   // 98

// -------- static device scratch --------
__device__ uint8_t        g_PQf8[(size_t)MAXV * NPQ]; // e4m3 P|Q (bxi folded into P), 102 MB
__device__ __nv_bfloat16  g_W2b[LNF * NPQ];           // bf16 [128 x 2048]
__device__ __nv_bfloat16  g_fb[(size_t)MAXV * LNF];   // bf16 feat
__device__ float          g_R[MAXV * SS];             // fp32 R
__device__ float          g_hacc[MAXV * SS];
__device__ int            g_cnt[MAXV];
__device__ int            g_fill[MAXV];
__device__ int            g_off[MAXV + 1];
__device__ int            g_bsum[MAXB];
__device__ int            g_ev[MAXE];
__device__ float          g_esc[MAXE];

// -------- side stream for CSR-chain overlap (created once, pre-baseline) --------
static cudaStream_t g_side = nullptr;
static cudaEvent_t  g_evf = nullptr, g_evj = nullptr;
struct SideInit {
    SideInit() {
        cudaStreamCreateWithFlags(&g_side, cudaStreamNonBlocking);
        cudaEventCreateWithFlags(&g_evf, cudaEventDisableTiming);
        cudaEventCreateWithFlags(&g_evj, cudaEventDisableTiming);
    }
};
static SideInit g_side_init;

__device__ __forceinline__ __half2 h2tanh_fast(__half2 x) {
    uint32_t xi = *(uint32_t*)&x, yi;
    asm("tanh.approx.f16x2 %0, %1;" : "=r"(yi) : "r"(xi));
    return *(__half2*)&yi;
}
__device__ __forceinline__ __half2 e4m3x2_to_h2(uint16_t x) {
    uint32_t r;
    asm("cvt.rn.f16x2.e4m3x2 %0, %1;" : "=r"(r) : "h"(x));
    return *(__half2*)&r;
}
// pack (v0 -> low byte, v1 -> high byte)
__device__ __forceinline__ uint16_t f32x2_to_e4m3x2(float v0, float v1) {
    uint16_t r;
    asm("cvt.rn.satfinite.e4m3x2.f32 %0, %1, %2;" : "=h"(r) : "f"(v1), "f"(v0));
    return r;
}

// ---------------- pack W2 (bf16 [K][N]) + cnt zero (fused) ----------------
__global__ void pack_w2_kernel(const float* __restrict__ Wxi, int V) {
    int idx = blockIdx.x * blockDim.x + threadIdx.x;
    if (idx < V) g_cnt[idx] = 0;
    if (idx >= LNF * NPQ) return;
    int k = idx / NPQ, j = idx - k * NPQ;
    float v = (j < 1024) ? Wxi[k * 1024 + j] : Wxi[(k + LNF) * 1024 + (j - 1024)];
    g_W2b[idx] = __float2bfloat16(v);
}

// ---------------- CSR build ----------------
__global__ void count_kernel(const int* __restrict__ Xn, int E) {
    int e = blockIdx.x * blockDim.x + threadIdx.x;
    if (e < E) atomicAdd(&g_cnt[Xn[e]], 1);
}

__global__ __launch_bounds__(SCAN_BLK) void scan1_kernel(int V) {
    __shared__ int s[SCAN_BLK];
    int i = blockIdx.x * SCAN_BLK + threadIdx.x;
    s[threadIdx.x] = (i < V) ? g_cnt[i] : 0;
    __syncthreads();
#pragma unroll
    for (int off = SCAN_BLK / 2; off > 0; off >>= 1) {
        if (threadIdx.x < off) s[threadIdx.x] += s[threadIdx.x + off];
        __syncthreads();
    }
    if (threadIdx.x == 0) g_bsum[blockIdx.x] = s[0];
}

__global__ __launch_bounds__(128) void scan2_kernel(int nb, int V) {
    __shared__ int s[128];
    int t = threadIdx.x;
    int v = (t < nb) ? g_bsum[t] : 0;
    s[t] = v;
    __syncthreads();
#pragma unroll
    for (int off = 1; off < 128; off <<= 1) {
        int x = (t >= off) ? s[t - off] : 0;
        __syncthreads();
        s[t] += x;
        __syncthreads();
    }
    if (t < nb) g_bsum[t] = s[t] - v;        // exclusive
    if (t == 127) g_off[V] = s[127];          // total
}

__global__ __launch_bounds__(SCAN_BLK) void scan3_kernel(int V) {
    __shared__ int s[SCAN_BLK];
    int i = blockIdx.x * SCAN_BLK + threadIdx.x;
    int v = (i < V) ? g_cnt[i] : 0;
    s[threadIdx.x] = v;
    __syncthreads();
#pragma unroll
    for (int off = 1; off < SCAN_BLK; off <<= 1) {
        int x = (threadIdx.x >= off) ? s[threadIdx.x - off] : 0;
        __syncthreads();
        s[threadIdx.x] += x;
        __syncthreads();
    }
    if (i < V) {
        g_off[i]  = g_bsum[blockIdx.x] + s[threadIdx.x] - v;   // exclusive
        g_fill[i] = 0;
    }
}

__global__ void fill_kernel(const int* __restrict__ Xn, const int* __restrict__ Xe,
                            const float* __restrict__ dg, int E) {
    int e = blockIdx.x * blockDim.x + threadIdx.x;
    if (e >= E) return;
    int u = Xn[e];
    int pos = g_off[u] + atomicAdd(&g_fill[u], 1);
    g_ev[pos]  = Xe[e];
    g_esc[pos] = MU_OVER_S / dg[e];
}

// ---------------- bf16 MMA GEMM: PQ[M x 2048] = featbf[M x 128] @ W2b ----------------
#define AS_STRIDE 136
#define SMEM_B_OFF (128 * AS_STRIDE)
#define GEMM_SMEM_BYTES (2 * 128 * AS_STRIDE * 2)

__device__ __forceinline__ void ldsm_x4(uint32_t& r0, uint32_t& r1, uint32_t& r2, uint32_t& r3,
                                        uint32_t addr) {
    asm volatile("ldmatrix.sync.aligned.m8n8.x4.shared.b16 {%0,%1,%2,%3}, [%4];"
                 : "=r"(r0), "=r"(r1), "=r"(r2), "=r"(r3) : "r"(addr));
}
__device__ __forceinline__ void ldsm_x4_t(uint32_t& r0, uint32_t& r1, uint32_t& r2, uint32_t& r3,
                                          uint32_t addr) {
    asm volatile("ldmatrix.sync.aligned.m8n8.x4.trans.shared.b16 {%0,%1,%2,%3}, [%4];"
                 : "=r"(r0), "=r"(r1), "=r"(r2), "=r"(r3) : "r"(addr));
}
__device__ __forceinline__ void mma_bf16(float* c, const uint32_t* a, uint32_t b0, uint32_t b1) {
    asm volatile(
        "mma.sync.aligned.m16n8k16.row.col.f32.bf16.bf16.f32 "
        "{%0,%1,%2,%3}, {%4,%5,%6,%7}, {%8,%9}, {%0,%1,%2,%3};\n"
        : "+f"(c[0]), "+f"(c[1]), "+f"(c[2]), "+f"(c[3])
        : "r"(a[0]), "r"(a[1]), "r"(a[2]), "r"(a[3]), "r"(b0), "r"(b1));
}
__device__ __forceinline__ void cp_async16(uint32_t saddr, const void* gaddr) {
    asm volatile("cp.async.cg.shared.global [%0], [%1], 16;" :: "r"(saddr), "l"(gaddr));
}

__device__ __forceinline__ void epi_store_pair(int row, int c, float v0, float v1, int M,
                                               const float* __restrict__ bxi) {
    if (row >= M) return;
    if (c < 1024) {
        v0 += __ldg(&bxi[c]);
        v1 += __ldg(&bxi[c + 1]);
    }
    *(uint16_t*)(g_PQf8 + (size_t)row * NPQ + c) = f32x2_to_e4m3x2(v0, v1);
}

__global__ __launch_bounds__(256) void gemm_bf16_kernel(const float* __restrict__ bxi, int M) {
    extern __shared__ __nv_bfloat16 smem[];

    const int tid  = threadIdx.x;
    const int warp = tid >> 5;
    const int lane = tid & 31;
    const int g    = lane >> 2;
    const int t4   = lane & 3;
    const int wm   = warp & 3;
    const int wn   = warp >> 2;
    const int row0 = blockIdx.y * 128;
    const int col0 = blockIdx.x * 128;

    uint32_t smem_base;
    asm("{ .reg .u64 t; cvta.to.shared.u64 t, %1; cvt.u32.u64 %0, t; }"
        : "=r"(smem_base) : "l"(smem));

#pragma unroll
    for (int i = 0; i < 8; ++i) {
        int c = tid + i * 256;
        int r = c >> 4;
        int seg = c & 15;
        int grow = row0 + r; if (grow >= M) grow = M - 1;
        cp_async16(smem_base + (uint32_t)(r * AS_STRIDE + seg * 8) * 2,
                   g_fb + (size_t)grow * LNF + seg * 8);
        cp_async16(smem_base + (uint32_t)(SMEM_B_OFF + r * AS_STRIDE + seg * 8) * 2,
                   g_W2b + (size_t)r * NPQ + col0 + seg * 8);
    }
    asm volatile("cp.async.commit_group;");
    asm volatile("cp.async.wait_group 0;");
    __syncthreads();

    float acc[2][8][4];
#pragma unroll
    for (int mt = 0; mt < 2; ++mt)
#pragma unroll
        for (int nt = 0; nt < 8; ++nt)
#pragma unroll
            for (int r = 0; r < 4; ++r) acc[mt][nt][r] = 0.0f;

#pragma unroll
    for (int ks = 0; ks < 8; ++ks) {
        const int kb = ks * 16;
        uint32_t a[2][4];
#pragma unroll
        for (int mt = 0; mt < 2; ++mt) {
            int ar = wm * 32 + mt * 16;
            uint32_t addr = smem_base +
                (uint32_t)((ar + (lane & 15)) * AS_STRIDE + kb + ((lane >> 4) << 3)) * 2;
            ldsm_x4(a[mt][0], a[mt][1], a[mt][2], a[mt][3], addr);
        }
#pragma unroll
        for (int np = 0; np < 4; ++np) {
            int nc = wn * 64 + np * 16;
            uint32_t b0, b1, b2, b3;
            uint32_t addr = smem_base +
                (uint32_t)(SMEM_B_OFF + (kb + (lane & 15)) * AS_STRIDE + nc + ((lane >> 4) << 3)) * 2;
            ldsm_x4_t(b0, b1, b2, b3, addr);
#pragma unroll
            for (int mt = 0; mt < 2; ++mt) {
                mma_bf16(acc[mt][np * 2],     a[mt], b0, b1);
                mma_bf16(acc[mt][np * 2 + 1], a[mt], b2, b3);
            }
        }
    }

#pragma unroll
    for (int mt = 0; mt < 2; ++mt) {
        int rlo = row0 + wm * 32 + mt * 16 + g;
#pragma unroll
        for (int nt = 0; nt < 8; ++nt) {
            int c = col0 + wn * 64 + nt * 8 + 2 * t4;
            epi_store_pair(rlo,     c, acc[mt][nt][0], acc[mt][nt][1], M, bxi);
            epi_store_pair(rlo + 8, c, acc[mt][nt][2], acc[mt][nt][3], M, bxi);
        }
    }
}

// ---------------- R kernel (fp32) + fused feat->bf16 conversion ----------------
#define RNODES 48
__global__ __launch_bounds__(256) void r_kernel(const float* __restrict__ feat,
                                                const float* __restrict__ Wrou,
                                                const float* __restrict__ brou, int V) {
    __shared__ float Ws[LNF * SS];
    __shared__ float fr[RNODES * LNF];
    const int tid = threadIdx.x;
    const int n0 = blockIdx.x * RNODES;

    for (int i = tid; i < LNF * SS; i += 256) Ws[i] = Wrou[i];
    for (int i = tid; i < RNODES * LNF / 4; i += 256) {
        int node = n0 + (i * 4) / LNF;
        if (node >= V) node = V - 1;
        int k = (i * 4) & (LNF - 1);
        *(float4*)&fr[i * 4] = *(const float4*)(feat + (size_t)node * LNF + k);
    }
    __syncthreads();

    for (int i = tid; i < RNODES * LNF / 2; i += 256) {
        int node = n0 + (i * 2) / LNF;
        if (node < V) {
            int k = (i * 2) & (LNF - 1);
            ((__nv_bfloat162*)(g_fb + (size_t)node * LNF + k))[0] =
                __floats2bfloat162_rn(fr[i * 2], fr[i * 2 + 1]);
        }
    }

    const int warp = tid >> 5, lane = tid & 31;
    float acc[6];
#pragma unroll
    for (int i = 0; i < 6; ++i) acc[i] = 0.0f;
    const float* fbase = &fr[warp * 6 * LNF];
#pragma unroll 16
    for (int k = 0; k < LNF; ++k) {
        float wv = Ws[k * SS + lane];
#pragma unroll
        for (int i = 0; i < 6; ++i) acc[i] = fmaf(fbase[i * LNF + k], wv, acc[i]);
    }
    float bb = brou[lane];
#pragma unroll
    for (int i = 0; i < 6; ++i) {
        int node = n0 + warp * 6 + i;
        if (node < V) g_R[node * SS + lane] = tanhf(acc[i] + bb);
    }
}

// ---------------- edge kernel: single pass, lane = output row, P+Q in fp8 ----------------
__global__ __launch_bounds__(256) void edge_kernel(int V) {
    __shared__ float rs[8][SS];
    const int warp = threadIdx.x >> 5;
    const int lane = threadIdx.x & 31;
    const int u = blockIdx.x * 8 + warp;
    if (u >= V) return;
    const int n = g_cnt[u];
    if (n == 0) return;
    const int start = g_off[u];

    rs[warp][lane] = g_R[u * SS + lane];
    __syncwarp();

    // P slice: 32 fp8 = 32B, converted once to fp16 registers
    const uint4* Pp = (const uint4*)(g_PQf8 + (size_t)u * NPQ + lane * 32);
    uint4 p0 = __ldcs(Pp), p1 = __ldcs(Pp + 1);
    const uint16_t* pa = (const uint16_t*)&p0;
    const uint16_t* pb = (const uint16_t*)&p1;
    __half2 ph[16];
#pragma unroll
    for (int k = 0; k < 8; ++k) {
        ph[k]     = e4m3x2_to_h2(pa[k]);
        ph[8 + k] = e4m3x2_to_h2(pb[k]);
    }

    float racc = 0.0f;
    for (int e = start; e < start + n; ++e) {
        const int v = g_ev[e];
        const float sc = g_esc[e];
        const uint4* qp = (const uint4*)(g_PQf8 + (size_t)v * NPQ + 1024 + lane * 32);
        uint4 q0 = qp[0];
        uint4 q1 = qp[1];
        const uint16_t* qa = (const uint16_t*)&q0;
        const uint16_t* qb = (const uint16_t*)&q1;

        float partial = 0.0f;
#pragma unroll
        for (int k = 0; k < 8; ++k) {
            float2 t = __half22float2(h2tanh_fast(__hadd2(ph[k], e4m3x2_to_h2(qa[k]))));
            partial = fmaf(t.x, rs[warp][2 * k],     partial);
            partial = fmaf(t.y, rs[warp][2 * k + 1], partial);
        }
#pragma unroll
        for (int k = 0; k < 8; ++k) {
            float2 t = __half22float2(h2tanh_fast(__hadd2(ph[8 + k], e4m3x2_to_h2(qb[k]))));
            partial = fmaf(t.x, rs[warp][16 + 2 * k], partial);
            partial = fmaf(t.y, rs[warp][17 + 2 * k], partial);
        }
        racc = fmaf(partial, sc, racc);
    }
    g_hacc[u * SS + lane] = racc;
}

// ---------------- output ----------------
__global__ __launch_bounds__(256) void out_kernel(const float* __restrict__ Wout,
                                                  const float* __restrict__ bout,
                                                  float* __restrict__ out, int V) {
    int gtid = blockIdx.x * blockDim.x + threadIdx.x;
    int vtx = gtid >> 5;
    int lane = threadIdx.x & 31;
    if (vtx >= V) return;

    float c = (float)g_cnt[vtx];
    float Hf = (c > 0.0f) ? c * (g_hacc[vtx * SS + lane] + g_R[vtx * SS + lane]) : 0.0f;

    float mine = 0.0f;
    float logits[CC];
#pragma unroll
    for (int j = 0; j < CC; ++j) {
        float p = Hf * Wout[lane * CC + j];
#pragma unroll
        for (int off = 16; off > 0; off >>= 1)
            p += __shfl_xor_sync(0xffffffffu, p, off);
        logits[j] = p + bout[j];
        if (j == lane) mine = logits[j];
    }
    float m = logits[0];
#pragma unroll
    for (int j = 1; j < CC; ++j) m = fmaxf(m, logits[j]);
    float se = 0.0f;
#pragma unroll
    for (int j = 0; j < CC; ++j) se += expf(logits[j] - m);
    float lse = m + logf(se);

    if (lane < CC) out[(size_t)vtx * CC + lane] = mine - lse;
}

// ---------------- launch ----------------
extern "C" void kernel_launch(void* const* d_in, const int* in_sizes, int n_in,
                              void* d_out, int out_size) {
    const float* feat = (const float*)d_in[0];
    const int*   Xn   = (const int*)d_in[1];
    const int*   Xe   = (const int*)d_in[2];
    const float* dg   = (const float*)d_in[3];
    const float* Wxi  = (const float*)d_in[4];
    const float* bxi  = (const float*)d_in[5];
    const float* Wrou = (const float*)d_in[6];
    const float* brou = (const float*)d_in[7];
    const float* Wout = (const float*)d_in[8];
    const float* bout = (const float*)d_in[9];
    float* out = (float*)d_out;

    const int V = in_sizes[0] / LNF;
    const int E = in_sizes[1];
    const int nb = (V + SCAN_BLK - 1) / SCAN_BLK;

    cudaFuncSetAttribute(gemm_bf16_kernel,
                         cudaFuncAttributeMaxDynamicSharedMemorySize, GEMM_SMEM_BYTES);

    // main stream: pack (zeroes g_cnt) first — both branches depend on it
    pack_w2_kernel<<<(LNF * NPQ + 255) / 256, 256>>>(Wxi, V);

    // fork: CSR chain on side stream, overlapped with r_kernel + GEMM
    cudaEventRecord(g_evf, 0);
    cudaStreamWaitEvent(g_side, g_evf, 0);
    count_kernel<<<(E + 255) / 256, 256, 0, g_side>>>(Xn, E);
    scan1_kernel<<<nb, SCAN_BLK, 0, g_side>>>(V);
    scan2_kernel<<<1, 128, 0, g_side>>>(nb, V);
    scan3_kernel<<<nb, SCAN_BLK, 0, g_side>>>(V);
    fill_kernel<<<(E + 255) / 256, 256, 0, g_side>>>(Xn, Xe, dg, E);
    cudaEventRecord(g_evj, g_side);

    // main: R (+feat->bf16) then GEMM
    r_kernel<<<(V + RNODES - 1) / RNODES, 256>>>(feat, Wrou, brou, V);
    dim3 ggrid(NPQ / 128, (V + 127) / 128);
    gemm_bf16_kernel<<<ggrid, 256, GEMM_SMEM_BYTES>>>(bxi, V);

    // join: edge needs CSR + PQ + R
    cudaStreamWaitEvent(0, g_evj, 0);
    edge_kernel<<<(V + 7) / 8, 256>>>(V);
    out_kernel<<<(V * 32 + 255) / 256, 256>>>(Wout, bout, out, V);
}

// round 14
// speedup vs baseline: 1.2412x; 1.0465x over previous
#include <cuda_runtime.h>
#include <cuda_fp16.h>
#include <cuda_bf16.h>
#include <math.h>
#include <stdint.h>

#define LNF 128      // feat dim
#define SS  32       // stat dim
#define CC  10       // classes
#define NPQ 2048     // GEMM N: P(1024) || Q(1024)
#define MAXV 50000
#define MAXE 200000
#define MU_OVER_S (0.9f / 32.0f)
#define SCAN_BLK 512
#define MAXB ((MAXV + SCAN_BLK - 1) / SCAN_BLK)   // 98
#define ECHUNK 4     // edges per warp in the balanced edge kernel

// -------- static device scratch --------
__device__ uint8_t        g_PQf8[(size_t)MAXV * NPQ]; // e4m3 P|Q (bxi folded into P), 102 MB
__device__ __nv_bfloat16  g_W2b[LNF * NPQ];           // bf16 [128 x 2048]
__device__ __nv_bfloat16  g_fb[(size_t)MAXV * LNF];   // bf16 feat
__device__ float          g_R[MAXV * SS];             // fp32 R
__device__ float          g_hacc[MAXV * SS];
__device__ int            g_cnt[MAXV];
__device__ int            g_fill[MAXV];
__device__ int            g_off[MAXV + 1];
__device__ int            g_bsum[MAXB];
__device__ int            g_ev[MAXE];                 // CSR: neighbor v per slot
__device__ int            g_eu[MAXE];                 // CSR: source u per slot
__device__ float          g_esc[MAXE];                // CSR: per-edge scale

// -------- side stream (created once, pre-baseline) --------
static cudaStream_t g_side = nullptr;
static cudaEvent_t  g_evf = nullptr, g_evj = nullptr;
struct SideInit {
    SideInit() {
        cudaStreamCreateWithFlags(&g_side, cudaStreamNonBlocking);
        cudaEventCreateWithFlags(&g_evf, cudaEventDisableTiming);
        cudaEventCreateWithFlags(&g_evj, cudaEventDisableTiming);
    }
};
static SideInit g_side_init;

__device__ __forceinline__ __half2 h2tanh_fast(__half2 x) {
    uint32_t xi = *(uint32_t*)&x, yi;
    asm("tanh.approx.f16x2 %0, %1;" : "=r"(yi) : "r"(xi));
    return *(__half2*)&yi;
}
__device__ __forceinline__ __half2 e4m3x2_to_h2(uint16_t x) {
    uint32_t r;
    asm("cvt.rn.f16x2.e4m3x2 %0, %1;" : "=r"(r) : "h"(x));
    return *(__half2*)&r;
}
__device__ __forceinline__ uint16_t f32x2_to_e4m3x2(float v0, float v1) {
    uint16_t r;
    asm("cvt.rn.satfinite.e4m3x2.f32 %0, %1, %2;" : "=h"(r) : "f"(v1), "f"(v0));
    return r;
}

// ---------------- pack W2 (bf16 [K][N]) + cnt zero (fused) ----------------
__global__ void pack_w2_kernel(const float* __restrict__ Wxi, int V) {
    int idx = blockIdx.x * blockDim.x + threadIdx.x;
    if (idx < V) g_cnt[idx] = 0;
    if (idx >= LNF * NPQ) return;
    int k = idx / NPQ, j = idx - k * NPQ;
    float v = (j < 1024) ? Wxi[k * 1024 + j] : Wxi[(k + LNF) * 1024 + (j - 1024)];
    g_W2b[idx] = __float2bfloat16(v);
}

// ---------------- CSR build (side stream) ----------------
__global__ void count_kernel(const int* __restrict__ Xn, int E, int V) {
    int t = blockIdx.x * blockDim.x + threadIdx.x;
    if (t < E) atomicAdd(&g_cnt[Xn[t]], 1);
    // zero hacc (atomics accumulate into it later)
    int total = gridDim.x * blockDim.x;
    for (int i = t; i < V * SS; i += total) g_hacc[i] = 0.0f;
}

__global__ __launch_bounds__(SCAN_BLK) void scan1_kernel(int V) {
    __shared__ int s[SCAN_BLK];
    int i = blockIdx.x * SCAN_BLK + threadIdx.x;
    s[threadIdx.x] = (i < V) ? g_cnt[i] : 0;
    __syncthreads();
#pragma unroll
    for (int off = SCAN_BLK / 2; off > 0; off >>= 1) {
        if (threadIdx.x < off) s[threadIdx.x] += s[threadIdx.x + off];
        __syncthreads();
    }
    if (threadIdx.x == 0) g_bsum[blockIdx.x] = s[0];
}

__global__ __launch_bounds__(128) void scan2_kernel(int nb, int V) {
    __shared__ int s[128];
    int t = threadIdx.x;
    int v = (t < nb) ? g_bsum[t] : 0;
    s[t] = v;
    __syncthreads();
#pragma unroll
    for (int off = 1; off < 128; off <<= 1) {
        int x = (t >= off) ? s[t - off] : 0;
        __syncthreads();
        s[t] += x;
        __syncthreads();
    }
    if (t < nb) g_bsum[t] = s[t] - v;        // exclusive
    if (t == 127) g_off[V] = s[127];
}

__global__ __launch_bounds__(SCAN_BLK) void scan3_kernel(int V) {
    __shared__ int s[SCAN_BLK];
    int i = blockIdx.x * SCAN_BLK + threadIdx.x;
    int v = (i < V) ? g_cnt[i] : 0;
    s[threadIdx.x] = v;
    __syncthreads();
#pragma unroll
    for (int off = 1; off < SCAN_BLK; off <<= 1) {
        int x = (threadIdx.x >= off) ? s[threadIdx.x - off] : 0;
        __syncthreads();
        s[threadIdx.x] += x;
        __syncthreads();
    }
    if (i < V) {
        g_off[i]  = g_bsum[blockIdx.x] + s[threadIdx.x] - v;   // exclusive
        g_fill[i] = 0;
    }
}

__global__ void fill_kernel(const int* __restrict__ Xn, const int* __restrict__ Xe,
                            const float* __restrict__ dg, int E) {
    int e = blockIdx.x * blockDim.x + threadIdx.x;
    if (e >= E) return;
    int u = Xn[e];
    int pos = g_off[u] + atomicAdd(&g_fill[u], 1);
    g_ev[pos]  = Xe[e];
    g_eu[pos]  = u;
    g_esc[pos] = MU_OVER_S / dg[e];
}

// ---------------- bf16 MMA GEMM: PQ[M x 2048] = featbf[M x 128] @ W2b ----------------
#define AS_STRIDE 136
#define SMEM_B_OFF (128 * AS_STRIDE)
#define GEMM_SMEM_BYTES (2 * 128 * AS_STRIDE * 2)

__device__ __forceinline__ void ldsm_x4(uint32_t& r0, uint32_t& r1, uint32_t& r2, uint32_t& r3,
                                        uint32_t addr) {
    asm volatile("ldmatrix.sync.aligned.m8n8.x4.shared.b16 {%0,%1,%2,%3}, [%4];"
                 : "=r"(r0), "=r"(r1), "=r"(r2), "=r"(r3) : "r"(addr));
}
__device__ __forceinline__ void ldsm_x4_t(uint32_t& r0, uint32_t& r1, uint32_t& r2, uint32_t& r3,
                                          uint32_t addr) {
    asm volatile("ldmatrix.sync.aligned.m8n8.x4.trans.shared.b16 {%0,%1,%2,%3}, [%4];"
                 : "=r"(r0), "=r"(r1), "=r"(r2), "=r"(r3) : "r"(addr));
}
__device__ __forceinline__ void mma_bf16(float* c, const uint32_t* a, uint32_t b0, uint32_t b1) {
    asm volatile(
        "mma.sync.aligned.m16n8k16.row.col.f32.bf16.bf16.f32 "
        "{%0,%1,%2,%3}, {%4,%5,%6,%7}, {%8,%9}, {%0,%1,%2,%3};\n"
        : "+f"(c[0]), "+f"(c[1]), "+f"(c[2]), "+f"(c[3])
        : "r"(a[0]), "r"(a[1]), "r"(a[2]), "r"(a[3]), "r"(b0), "r"(b1));
}
__device__ __forceinline__ void cp_async16(uint32_t saddr, const void* gaddr) {
    asm volatile("cp.async.cg.shared.global [%0], [%1], 16;" :: "r"(saddr), "l"(gaddr));
}

__device__ __forceinline__ void epi_store_pair(int row, int c, float v0, float v1, int M,
                                               const float* __restrict__ bxi) {
    if (row >= M) return;
    if (c < 1024) {
        v0 += __ldg(&bxi[c]);
        v1 += __ldg(&bxi[c + 1]);
    }
    *(uint16_t*)(g_PQf8 + (size_t)row * NPQ + c) = f32x2_to_e4m3x2(v0, v1);
}

__global__ __launch_bounds__(256) void gemm_bf16_kernel(const float* __restrict__ bxi, int M) {
    extern __shared__ __nv_bfloat16 smem[];

    const int tid  = threadIdx.x;
    const int warp = tid >> 5;
    const int lane = tid & 31;
    const int g    = lane >> 2;
    const int t4   = lane & 3;
    const int wm   = warp & 3;
    const int wn   = warp >> 2;
    const int row0 = blockIdx.y * 128;
    const int col0 = blockIdx.x * 128;

    uint32_t smem_base;
    asm("{ .reg .u64 t; cvta.to.shared.u64 t, %1; cvt.u32.u64 %0, t; }"
        : "=r"(smem_base) : "l"(smem));

#pragma unroll
    for (int i = 0; i < 8; ++i) {
        int c = tid + i * 256;
        int r = c >> 4;
        int seg = c & 15;
        int grow = row0 + r; if (grow >= M) grow = M - 1;
        cp_async16(smem_base + (uint32_t)(r * AS_STRIDE + seg * 8) * 2,
                   g_fb + (size_t)grow * LNF + seg * 8);
        cp_async16(smem_base + (uint32_t)(SMEM_B_OFF + r * AS_STRIDE + seg * 8) * 2,
                   g_W2b + (size_t)r * NPQ + col0 + seg * 8);
    }
    asm volatile("cp.async.commit_group;");
    asm volatile("cp.async.wait_group 0;");
    __syncthreads();

    float acc[2][8][4];
#pragma unroll
    for (int mt = 0; mt < 2; ++mt)
#pragma unroll
        for (int nt = 0; nt < 8; ++nt)
#pragma unroll
            for (int r = 0; r < 4; ++r) acc[mt][nt][r] = 0.0f;

#pragma unroll
    for (int ks = 0; ks < 8; ++ks) {
        const int kb = ks * 16;
        uint32_t a[2][4];
#pragma unroll
        for (int mt = 0; mt < 2; ++mt) {
            int ar = wm * 32 + mt * 16;
            uint32_t addr = smem_base +
                (uint32_t)((ar + (lane & 15)) * AS_STRIDE + kb + ((lane >> 4) << 3)) * 2;
            ldsm_x4(a[mt][0], a[mt][1], a[mt][2], a[mt][3], addr);
        }
#pragma unroll
        for (int np = 0; np < 4; ++np) {
            int nc = wn * 64 + np * 16;
            uint32_t b0, b1, b2, b3;
            uint32_t addr = smem_base +
                (uint32_t)(SMEM_B_OFF + (kb + (lane & 15)) * AS_STRIDE + nc + ((lane >> 4) << 3)) * 2;
            ldsm_x4_t(b0, b1, b2, b3, addr);
#pragma unroll
            for (int mt = 0; mt < 2; ++mt) {
                mma_bf16(acc[mt][np * 2],     a[mt], b0, b1);
                mma_bf16(acc[mt][np * 2 + 1], a[mt], b2, b3);
            }
        }
    }

#pragma unroll
    for (int mt = 0; mt < 2; ++mt) {
        int rlo = row0 + wm * 32 + mt * 16 + g;
#pragma unroll
        for (int nt = 0; nt < 8; ++nt) {
            int c = col0 + wn * 64 + nt * 8 + 2 * t4;
            epi_store_pair(rlo,     c, acc[mt][nt][0], acc[mt][nt][1], M, bxi);
            epi_store_pair(rlo + 8, c, acc[mt][nt][2], acc[mt][nt][3], M, bxi);
        }
    }
}

// ---------------- R kernel (fp32) + fused feat->bf16 conversion ----------------
#define RNODES 48
__global__ __launch_bounds__(256) void r_kernel(const float* __restrict__ feat,
                                                const float* __restrict__ Wrou,
                                                const float* __restrict__ brou, int V) {
    __shared__ float Ws[LNF * SS];
    __shared__ float fr[RNODES * LNF];
    const int tid = threadIdx.x;
    const int n0 = blockIdx.x * RNODES;

    for (int i = tid; i < LNF * SS; i += 256) Ws[i] = Wrou[i];
    for (int i = tid; i < RNODES * LNF / 4; i += 256) {
        int node = n0 + (i * 4) / LNF;
        if (node >= V) node = V - 1;
        int k = (i * 4) & (LNF - 1);
        *(float4*)&fr[i * 4] = *(const float4*)(feat + (size_t)node * LNF + k);
    }
    __syncthreads();

    for (int i = tid; i < RNODES * LNF / 2; i += 256) {
        int node = n0 + (i * 2) / LNF;
        if (node < V) {
            int k = (i * 2) & (LNF - 1);
            ((__nv_bfloat162*)(g_fb + (size_t)node * LNF + k))[0] =
                __floats2bfloat162_rn(fr[i * 2], fr[i * 2 + 1]);
        }
    }

    const int warp = tid >> 5, lane = tid & 31;
    float acc[6];
#pragma unroll
    for (int i = 0; i < 6; ++i) acc[i] = 0.0f;
    const float* fbase = &fr[warp * 6 * LNF];
#pragma unroll 16
    for (int k = 0; k < LNF; ++k) {
        float wv = Ws[k * SS + lane];
#pragma unroll
        for (int i = 0; i < 6; ++i) acc[i] = fmaf(fbase[i * LNF + k], wv, acc[i]);
    }
    float bb = brou[lane];
#pragma unroll
    for (int i = 0; i < 6; ++i) {
        int node = n0 + warp * 6 + i;
        if (node < V) g_R[node * SS + lane] = tanhf(acc[i] + bb);
    }
}

// ---------------- balanced edge kernel: warp = 4 consecutive CSR slots ----------------
// CSR slots are grouped by u (fill order), so u changes rarely inside a chunk.
// lane i computes output row i; per-u state (P frag + R row) reloads on boundary;
// partial results flushed with atomicAdd (few contenders per address).
__global__ __launch_bounds__(256) void edge_bal_kernel(int E) {
    __shared__ float rs[8][SS];
    const int warp = threadIdx.x >> 5;
    const int lane = threadIdx.x & 31;
    const int e0 = (blockIdx.x * 8 + warp) * ECHUNK;
    if (e0 >= E) return;
    const int e1 = (e0 + ECHUNK < E) ? e0 + ECHUNK : E;

    int cur_u = -1;
    float racc = 0.0f;
    __half2 ph[16];

    for (int e = e0; e < e1; ++e) {
        const int u = g_eu[e];
        if (u != cur_u) {
            if (cur_u >= 0) {
                atomicAdd(&g_hacc[cur_u * SS + lane], racc);
                racc = 0.0f;
            }
            cur_u = u;
            rs[warp][lane] = g_R[u * SS + lane];
            __syncwarp();
            const uint4* Pp = (const uint4*)(g_PQf8 + (size_t)u * NPQ + lane * 32);
            uint4 p0 = Pp[0], p1 = Pp[1];
            const uint16_t* pa = (const uint16_t*)&p0;
            const uint16_t* pb = (const uint16_t*)&p1;
#pragma unroll
            for (int k = 0; k < 8; ++k) {
                ph[k]     = e4m3x2_to_h2(pa[k]);
                ph[8 + k] = e4m3x2_to_h2(pb[k]);
            }
        }

        const int v = g_ev[e];
        const float sc = g_esc[e];
        const uint4* qp = (const uint4*)(g_PQf8 + (size_t)v * NPQ + 1024 + lane * 32);
        uint4 q0 = qp[0];
        uint4 q1 = qp[1];
        const uint16_t* qa = (const uint16_t*)&q0;
        const uint16_t* qb = (const uint16_t*)&q1;

        float partial = 0.0f;
#pragma unroll
        for (int k = 0; k < 8; ++k) {
            float2 t = __half22float2(h2tanh_fast(__hadd2(ph[k], e4m3x2_to_h2(qa[k]))));
            partial = fmaf(t.x, rs[warp][2 * k],     partial);
            partial = fmaf(t.y, rs[warp][2 * k + 1], partial);
        }
#pragma unroll
        for (int k = 0; k < 8; ++k) {
            float2 t = __half22float2(h2tanh_fast(__hadd2(ph[8 + k], e4m3x2_to_h2(qb[k]))));
            partial = fmaf(t.x, rs[warp][16 + 2 * k], partial);
            partial = fmaf(t.y, rs[warp][17 + 2 * k], partial);
        }
        racc = fmaf(partial, sc, racc);
    }
    if (cur_u >= 0)
        atomicAdd(&g_hacc[cur_u * SS + lane], racc);
}

// ---------------- output ----------------
__global__ __launch_bounds__(256) void out_kernel(const float* __restrict__ Wout,
                                                  const float* __restrict__ bout,
                                                  float* __restrict__ out, int V) {
    int gtid = blockIdx.x * blockDim.x + threadIdx.x;
    int vtx = gtid >> 5;
    int lane = threadIdx.x & 31;
    if (vtx >= V) return;

    float c = (float)g_cnt[vtx];
    float Hf = (c > 0.0f) ? c * (g_hacc[vtx * SS + lane] + g_R[vtx * SS + lane]) : 0.0f;

    float mine = 0.0f;
    float logits[CC];
#pragma unroll
    for (int j = 0; j < CC; ++j) {
        float p = Hf * Wout[lane * CC + j];
#pragma unroll
        for (int off = 16; off > 0; off >>= 1)
            p += __shfl_xor_sync(0xffffffffu, p, off);
        logits[j] = p + bout[j];
        if (j == lane) mine = logits[j];
    }
    float m = logits[0];
#pragma unroll
    for (int j = 1; j < CC; ++j) m = fmaxf(m, logits[j]);
    float se = 0.0f;
#pragma unroll
    for (int j = 0; j < CC; ++j) se += expf(logits[j] - m);
    float lse = m + logf(se);

    if (lane < CC) out[(size_t)vtx * CC + lane] = mine - lse;
}

// ---------------- launch ----------------
extern "C" void kernel_launch(void* const* d_in, const int* in_sizes, int n_in,
                              void* d_out, int out_size) {
    const float* feat = (const float*)d_in[0];
    const int*   Xn   = (const int*)d_in[1];
    const int*   Xe   = (const int*)d_in[2];
    const float* dg   = (const float*)d_in[3];
    const float* Wxi  = (const float*)d_in[4];
    const float* bxi  = (const float*)d_in[5];
    const float* Wrou = (const float*)d_in[6];
    const float* brou = (const float*)d_in[7];
    const float* Wout = (const float*)d_in[8];
    const float* bout = (const float*)d_in[9];
    float* out = (float*)d_out;

    const int V = in_sizes[0] / LNF;
    const int E = in_sizes[1];
    const int nb = (V + SCAN_BLK - 1) / SCAN_BLK;

    cudaFuncSetAttribute(gemm_bf16_kernel,
                         cudaFuncAttributeMaxDynamicSharedMemorySize, GEMM_SMEM_BYTES);

    // main: pack W2 (zeroes g_cnt) — both branches depend on it
    pack_w2_kernel<<<(LNF * NPQ + 255) / 256, 256>>>(Wxi, V);

    // fork: CSR chain (+hacc zero) on side stream
    cudaEventRecord(g_evf, 0);
    cudaStreamWaitEvent(g_side, g_evf, 0);
    count_kernel<<<(E + 255) / 256, 256, 0, g_side>>>(Xn, E, V);
    scan1_kernel<<<nb, SCAN_BLK, 0, g_side>>>(V);
    scan2_kernel<<<1, 128, 0, g_side>>>(nb, V);
    scan3_kernel<<<nb, SCAN_BLK, 0, g_side>>>(V);
    fill_kernel<<<(E + 255) / 256, 256, 0, g_side>>>(Xn, Xe, dg, E);
    cudaEventRecord(g_evj, g_side);

    // main: R (+feat->bf16) then GEMM
    r_kernel<<<(V + RNODES - 1) / RNODES, 256>>>(feat, Wrou, brou, V);
    dim3 ggrid(NPQ / 128, (V + 127) / 128);
    gemm_bf16_kernel<<<ggrid, 256, GEMM_SMEM_BYTES>>>(bxi, V);

    // join: edge needs CSR + PQ + R
    cudaStreamWaitEvent(0, g_evj, 0);
    const int nchunks = (E + ECHUNK - 1) / ECHUNK;
    edge_bal_kernel<<<(nchunks + 7) / 8, 256>>>(E);
    out_kernel<<<(V * 32 + 255) / 256, 256>>>(Wout, bout, out, V);
}

// round 15
// speedup vs baseline: 1.3009x; 1.0481x over previous
#include <cuda_runtime.h>
#include <cuda_fp16.h>
#include <cuda_bf16.h>
#include <math.h>
#include <stdint.h>

#define LNF 128      // feat dim
#define SS  32       // stat dim
#define CC  10       // classes
#define NPQ 2048     // P(1024) || Q(1024)
#define NTOT 2176    // GEMM N: 2048 PQ + 32 R + 96 pad  (17 * 128)
#define MAXV 50000
#define MAXE 200000
#define MU_OVER_S (0.9f / 32.0f)
#define SCAN_BLK 512
#define MAXB ((MAXV + SCAN_BLK - 1) / SCAN_BLK)   // 98
#define ECHUNK 8     // edges per warp in the balanced edge kernel

// -------- static device scratch --------
__device__ uint8_t        g_PQf8[(size_t)MAXV * NPQ]; // e4m3 P|Q (bxi folded into P), 102 MB
__device__ __nv_bfloat16  g_W2b[LNF * NTOT];          // bf16 [128 x 2176]
__device__ __nv_bfloat16  g_fb[(size_t)MAXV * LNF];   // bf16 feat
__device__ float          g_R[MAXV * SS];             // fp32 R (from GEMM epilogue)
__device__ float          g_hacc[MAXV * SS];
__device__ int            g_cnt[MAXV];
__device__ int            g_fill[MAXV];
__device__ int            g_off[MAXV + 1];
__device__ int            g_bsum[MAXB];
__device__ int            g_ev[MAXE];                 // CSR: neighbor v per slot
__device__ int            g_eu[MAXE];                 // CSR: source u per slot
__device__ float          g_esc[MAXE];                // CSR: per-edge scale

// -------- side stream (created once, pre-baseline) --------
static cudaStream_t g_side = nullptr;
static cudaEvent_t  g_evf = nullptr, g_evj = nullptr;
struct SideInit {
    SideInit() {
        cudaStreamCreateWithFlags(&g_side, cudaStreamNonBlocking);
        cudaEventCreateWithFlags(&g_evf, cudaEventDisableTiming);
        cudaEventCreateWithFlags(&g_evj, cudaEventDisableTiming);
    }
};
static SideInit g_side_init;

__device__ __forceinline__ __half2 h2tanh_fast(__half2 x) {
    uint32_t xi = *(uint32_t*)&x, yi;
    asm("tanh.approx.f16x2 %0, %1;" : "=r"(yi) : "r"(xi));
    return *(__half2*)&yi;
}
__device__ __forceinline__ __half2 e4m3x2_to_h2(uint16_t x) {
    uint32_t r;
    asm("cvt.rn.f16x2.e4m3x2 %0, %1;" : "=r"(r) : "h"(x));
    return *(__half2*)&r;
}
__device__ __forceinline__ uint16_t f32x2_to_e4m3x2(float v0, float v1) {
    uint16_t r;
    asm("cvt.rn.satfinite.e4m3x2.f32 %0, %1, %2;" : "=h"(r) : "f"(v1), "f"(v0));
    return r;
}

// ---------------- pack W2 (bf16 [K][2176]) + cnt zero (fused) ----------------
__global__ void pack_w2_kernel(const float* __restrict__ Wxi,
                               const float* __restrict__ Wrou, int V) {
    int idx = blockIdx.x * blockDim.x + threadIdx.x;
    if (idx < V) g_cnt[idx] = 0;
    if (idx >= LNF * NTOT) return;
    int k = idx / NTOT, j = idx - k * NTOT;
    float v;
    if (j < 1024)       v = Wxi[k * 1024 + j];
    else if (j < 2048)  v = Wxi[(k + LNF) * 1024 + (j - 1024)];
    else if (j < 2080)  v = Wrou[k * SS + (j - 2048)];
    else                v = 0.0f;
    g_W2b[idx] = __float2bfloat16(v);
}

// ---------------- feat -> bf16 ----------------
__global__ void cvt_feat_kernel(const float* __restrict__ feat, int npairs) {
    int idx = blockIdx.x * blockDim.x + threadIdx.x;
    if (idx >= npairs) return;
    float2 f = ((const float2*)feat)[idx];
    ((__nv_bfloat162*)g_fb)[idx] = __floats2bfloat162_rn(f.x, f.y);
}

// ---------------- CSR build (side stream) ----------------
__global__ void count_kernel(const int* __restrict__ Xn, int E, int V) {
    int t = blockIdx.x * blockDim.x + threadIdx.x;
    if (t < E) atomicAdd(&g_cnt[Xn[t]], 1);
    int total = gridDim.x * blockDim.x;
    for (int i = t; i < V * SS; i += total) g_hacc[i] = 0.0f;
}

__global__ __launch_bounds__(SCAN_BLK) void scan1_kernel(int V) {
    __shared__ int s[SCAN_BLK];
    int i = blockIdx.x * SCAN_BLK + threadIdx.x;
    s[threadIdx.x] = (i < V) ? g_cnt[i] : 0;
    __syncthreads();
#pragma unroll
    for (int off = SCAN_BLK / 2; off > 0; off >>= 1) {
        if (threadIdx.x < off) s[threadIdx.x] += s[threadIdx.x + off];
        __syncthreads();
    }
    if (threadIdx.x == 0) g_bsum[blockIdx.x] = s[0];
}

__global__ __launch_bounds__(128) void scan2_kernel(int nb, int V) {
    __shared__ int s[128];
    int t = threadIdx.x;
    int v = (t < nb) ? g_bsum[t] : 0;
    s[t] = v;
    __syncthreads();
#pragma unroll
    for (int off = 1; off < 128; off <<= 1) {
        int x = (t >= off) ? s[t - off] : 0;
        __syncthreads();
        s[t] += x;
        __syncthreads();
    }
    if (t < nb) g_bsum[t] = s[t] - v;        // exclusive
    if (t == 127) g_off[V] = s[127];
}

__global__ __launch_bounds__(SCAN_BLK) void scan3_kernel(int V) {
    __shared__ int s[SCAN_BLK];
    int i = blockIdx.x * SCAN_BLK + threadIdx.x;
    int v = (i < V) ? g_cnt[i] : 0;
    s[threadIdx.x] = v;
    __syncthreads();
#pragma unroll
    for (int off = 1; off < SCAN_BLK; off <<= 1) {
        int x = (threadIdx.x >= off) ? s[threadIdx.x - off] : 0;
        __syncthreads();
        s[threadIdx.x] += x;
        __syncthreads();
    }
    if (i < V) {
        g_off[i]  = g_bsum[blockIdx.x] + s[threadIdx.x] - v;   // exclusive
        g_fill[i] = 0;
    }
}

__global__ void fill_kernel(const int* __restrict__ Xn, const int* __restrict__ Xe,
                            const float* __restrict__ dg, int E) {
    int e = blockIdx.x * blockDim.x + threadIdx.x;
    if (e >= E) return;
    int u = Xn[e];
    int pos = g_off[u] + atomicAdd(&g_fill[u], 1);
    g_ev[pos]  = Xe[e];
    g_eu[pos]  = u;
    g_esc[pos] = MU_OVER_S / dg[e];
}

// ---------------- bf16 MMA GEMM: [M x 2176] = featbf[M x 128] @ W2b ----------------
#define AS_STRIDE 136
#define SMEM_B_OFF (128 * AS_STRIDE)
#define GEMM_SMEM_BYTES (2 * 128 * AS_STRIDE * 2)

__device__ __forceinline__ void ldsm_x4(uint32_t& r0, uint32_t& r1, uint32_t& r2, uint32_t& r3,
                                        uint32_t addr) {
    asm volatile("ldmatrix.sync.aligned.m8n8.x4.shared.b16 {%0,%1,%2,%3}, [%4];"
                 : "=r"(r0), "=r"(r1), "=r"(r2), "=r"(r3) : "r"(addr));
}
__device__ __forceinline__ void ldsm_x4_t(uint32_t& r0, uint32_t& r1, uint32_t& r2, uint32_t& r3,
                                          uint32_t addr) {
    asm volatile("ldmatrix.sync.aligned.m8n8.x4.trans.shared.b16 {%0,%1,%2,%3}, [%4];"
                 : "=r"(r0), "=r"(r1), "=r"(r2), "=r"(r3) : "r"(addr));
}
__device__ __forceinline__ void mma_bf16(float* c, const uint32_t* a, uint32_t b0, uint32_t b1) {
    asm volatile(
        "mma.sync.aligned.m16n8k16.row.col.f32.bf16.bf16.f32 "
        "{%0,%1,%2,%3}, {%4,%5,%6,%7}, {%8,%9}, {%0,%1,%2,%3};\n"
        : "+f"(c[0]), "+f"(c[1]), "+f"(c[2]), "+f"(c[3])
        : "r"(a[0]), "r"(a[1]), "r"(a[2]), "r"(a[3]), "r"(b0), "r"(b1));
}
__device__ __forceinline__ void cp_async16(uint32_t saddr, const void* gaddr) {
    asm volatile("cp.async.cg.shared.global [%0], [%1], 16;" :: "r"(saddr), "l"(gaddr));
}

__device__ __forceinline__ void epi_store_pair(int row, int c, float v0, float v1, int M,
                                               const float* __restrict__ bxi,
                                               const float* __restrict__ brou) {
    if (row >= M) return;
    if (c < 1024) {
        v0 += __ldg(&bxi[c]);
        v1 += __ldg(&bxi[c + 1]);
        *(uint16_t*)(g_PQf8 + (size_t)row * NPQ + c) = f32x2_to_e4m3x2(v0, v1);
    } else if (c < 2048) {
        *(uint16_t*)(g_PQf8 + (size_t)row * NPQ + c) = f32x2_to_e4m3x2(v0, v1);
    } else if (c < 2080) {
        int j = c - 2048;
        float2 rr;
        rr.x = tanhf(v0 + __ldg(&brou[j]));
        rr.y = tanhf(v1 + __ldg(&brou[j + 1]));
        *(float2*)(g_R + (size_t)row * SS + j) = rr;
    }
}

__global__ __launch_bounds__(256) void gemm_bf16_kernel(const float* __restrict__ bxi,
                                                        const float* __restrict__ brou, int M) {
    extern __shared__ __nv_bfloat16 smem[];

    const int tid  = threadIdx.x;
    const int warp = tid >> 5;
    const int lane = tid & 31;
    const int g    = lane >> 2;
    const int t4   = lane & 3;
    const int wm   = warp & 3;
    const int wn   = warp >> 2;
    const int row0 = blockIdx.y * 128;
    const int col0 = blockIdx.x * 128;

    uint32_t smem_base;
    asm("{ .reg .u64 t; cvta.to.shared.u64 t, %1; cvt.u32.u64 %0, t; }"
        : "=r"(smem_base) : "l"(smem));

#pragma unroll
    for (int i = 0; i < 8; ++i) {
        int c = tid + i * 256;
        int r = c >> 4;
        int seg = c & 15;
        int grow = row0 + r; if (grow >= M) grow = M - 1;
        cp_async16(smem_base + (uint32_t)(r * AS_STRIDE + seg * 8) * 2,
                   g_fb + (size_t)grow * LNF + seg * 8);
        cp_async16(smem_base + (uint32_t)(SMEM_B_OFF + r * AS_STRIDE + seg * 8) * 2,
                   g_W2b + (size_t)r * NTOT + col0 + seg * 8);
    }
    asm volatile("cp.async.commit_group;");
    asm volatile("cp.async.wait_group 0;");
    __syncthreads();

    float acc[2][8][4];
#pragma unroll
    for (int mt = 0; mt < 2; ++mt)
#pragma unroll
        for (int nt = 0; nt < 8; ++nt)
#pragma unroll
            for (int r = 0; r < 4; ++r) acc[mt][nt][r] = 0.0f;

#pragma unroll
    for (int ks = 0; ks < 8; ++ks) {
        const int kb = ks * 16;
        uint32_t a[2][4];
#pragma unroll
        for (int mt = 0; mt < 2; ++mt) {
            int ar = wm * 32 + mt * 16;
            uint32_t addr = smem_base +
                (uint32_t)((ar + (lane & 15)) * AS_STRIDE + kb + ((lane >> 4) << 3)) * 2;
            ldsm_x4(a[mt][0], a[mt][1], a[mt][2], a[mt][3], addr);
        }
#pragma unroll
        for (int np = 0; np < 4; ++np) {
            int nc = wn * 64 + np * 16;
            uint32_t b0, b1, b2, b3;
            uint32_t addr = smem_base +
                (uint32_t)(SMEM_B_OFF + (kb + (lane & 15)) * AS_STRIDE + nc + ((lane >> 4) << 3)) * 2;
            ldsm_x4_t(b0, b1, b2, b3, addr);
#pragma unroll
            for (int mt = 0; mt < 2; ++mt) {
                mma_bf16(acc[mt][np * 2],     a[mt], b0, b1);
                mma_bf16(acc[mt][np * 2 + 1], a[mt], b2, b3);
            }
        }
    }

#pragma unroll
    for (int mt = 0; mt < 2; ++mt) {
        int rlo = row0 + wm * 32 + mt * 16 + g;
#pragma unroll
        for (int nt = 0; nt < 8; ++nt) {
            int c = col0 + wn * 64 + nt * 8 + 2 * t4;
            epi_store_pair(rlo,     c, acc[mt][nt][0], acc[mt][nt][1], M, bxi, brou);
            epi_store_pair(rlo + 8, c, acc[mt][nt][2], acc[mt][nt][3], M, bxi, brou);
        }
    }
}

// ---------------- balanced edge kernel: warp = ECHUNK consecutive CSR slots ----------------
__global__ __launch_bounds__(256) void edge_bal_kernel(int E) {
    __shared__ float rs[8][SS];
    const int warp = threadIdx.x >> 5;
    const int lane = threadIdx.x & 31;
    const int e0 = (blockIdx.x * 8 + warp) * ECHUNK;
    if (e0 >= E) return;
    const int e1 = (e0 + ECHUNK < E) ? e0 + ECHUNK : E;

    int cur_u = -1;
    float racc = 0.0f;
    __half2 ph[16];

    for (int e = e0; e < e1; ++e) {
        const int u = g_eu[e];
        if (u != cur_u) {
            if (cur_u >= 0) {
                atomicAdd(&g_hacc[cur_u * SS + lane], racc);
                racc = 0.0f;
            }
            cur_u = u;
            rs[warp][lane] = g_R[u * SS + lane];
            __syncwarp();
            const uint4* Pp = (const uint4*)(g_PQf8 + (size_t)u * NPQ + lane * 32);
            uint4 p0 = Pp[0], p1 = Pp[1];
            const uint16_t* pa = (const uint16_t*)&p0;
            const uint16_t* pb = (const uint16_t*)&p1;
#pragma unroll
            for (int k = 0; k < 8; ++k) {
                ph[k]     = e4m3x2_to_h2(pa[k]);
                ph[8 + k] = e4m3x2_to_h2(pb[k]);
            }
        }

        const int v = g_ev[e];
        const float sc = g_esc[e];
        const uint4* qp = (const uint4*)(g_PQf8 + (size_t)v * NPQ + 1024 + lane * 32);
        uint4 q0 = qp[0];
        uint4 q1 = qp[1];
        const uint16_t* qa = (const uint16_t*)&q0;
        const uint16_t* qb = (const uint16_t*)&q1;

        float partial = 0.0f;
#pragma unroll
        for (int k = 0; k < 8; ++k) {
            float2 t = __half22float2(h2tanh_fast(__hadd2(ph[k], e4m3x2_to_h2(qa[k]))));
            partial = fmaf(t.x, rs[warp][2 * k],     partial);
            partial = fmaf(t.y, rs[warp][2 * k + 1], partial);
        }
#pragma unroll
        for (int k = 0; k < 8; ++k) {
            float2 t = __half22float2(h2tanh_fast(__hadd2(ph[8 + k], e4m3x2_to_h2(qb[k]))));
            partial = fmaf(t.x, rs[warp][16 + 2 * k], partial);
            partial = fmaf(t.y, rs[warp][17 + 2 * k], partial);
        }
        racc = fmaf(partial, sc, racc);
    }
    if (cur_u >= 0)
        atomicAdd(&g_hacc[cur_u * SS + lane], racc);
}

// ---------------- output ----------------
__global__ __launch_bounds__(256) void out_kernel(const float* __restrict__ Wout,
                                                  const float* __restrict__ bout,
                                                  float* __restrict__ out, int V) {
    int gtid = blockIdx.x * blockDim.x + threadIdx.x;
    int vtx = gtid >> 5;
    int lane = threadIdx.x & 31;
    if (vtx >= V) return;

    float c = (float)g_cnt[vtx];
    float Hf = (c > 0.0f) ? c * (g_hacc[vtx * SS + lane] + g_R[vtx * SS + lane]) : 0.0f;

    float mine = 0.0f;
    float logits[CC];
#pragma unroll
    for (int j = 0; j < CC; ++j) {
        float p = Hf * Wout[lane * CC + j];
#pragma unroll
        for (int off = 16; off > 0; off >>= 1)
            p += __shfl_xor_sync(0xffffffffu, p, off);
        logits[j] = p + bout[j];
        if (j == lane) mine = logits[j];
    }
    float m = logits[0];
#pragma unroll
    for (int j = 1; j < CC; ++j) m = fmaxf(m, logits[j]);
    float se = 0.0f;
#pragma unroll
    for (int j = 0; j < CC; ++j) se += expf(logits[j] - m);
    float lse = m + logf(se);

    if (lane < CC) out[(size_t)vtx * CC + lane] = mine - lse;
}

// ---------------- launch ----------------
extern "C" void kernel_launch(void* const* d_in, const int* in_sizes, int n_in,
                              void* d_out, int out_size) {
    const float* feat = (const float*)d_in[0];
    const int*   Xn   = (const int*)d_in[1];
    const int*   Xe   = (const int*)d_in[2];
    const float* dg   = (const float*)d_in[3];
    const float* Wxi  = (const float*)d_in[4];
    const float* bxi  = (const float*)d_in[5];
    const float* Wrou = (const float*)d_in[6];
    const float* brou = (const float*)d_in[7];
    const float* Wout = (const float*)d_in[8];
    const float* bout = (const float*)d_in[9];
    float* out = (float*)d_out;

    const int V = in_sizes[0] / LNF;
    const int E = in_sizes[1];
    const int nb = (V + SCAN_BLK - 1) / SCAN_BLK;

    cudaFuncSetAttribute(gemm_bf16_kernel,
                         cudaFuncAttributeMaxDynamicSharedMemorySize, GEMM_SMEM_BYTES);

    // main: pack W2 (zeroes g_cnt) — both branches depend on g_cnt
    pack_w2_kernel<<<(LNF * NTOT + 255) / 256, 256>>>(Wxi, Wrou, V);

    // fork: CSR chain (+hacc zero) on side stream
    cudaEventRecord(g_evf, 0);
    cudaStreamWaitEvent(g_side, g_evf, 0);
    count_kernel<<<(E + 255) / 256, 256, 0, g_side>>>(Xn, E, V);
    scan1_kernel<<<nb, SCAN_BLK, 0, g_side>>>(V);
    scan2_kernel<<<1, 128, 0, g_side>>>(nb, V);
    scan3_kernel<<<nb, SCAN_BLK, 0, g_side>>>(V);
    fill_kernel<<<(E + 255) / 256, 256, 0, g_side>>>(Xn, Xe, dg, E);
    cudaEventRecord(g_evj, g_side);

    // main: feat->bf16, then fused GEMM (PQ fp8 + R fp32)
    cvt_feat_kernel<<<(V * LNF / 2 + 255) / 256, 256>>>(feat, V * LNF / 2);
    dim3 ggrid(NTOT / 128, (V + 127) / 128);
    gemm_bf16_kernel<<<ggrid, 256, GEMM_SMEM_BYTES>>>(bxi, brou, V);

    // join: edge needs CSR + PQ + R
    cudaStreamWaitEvent(0, g_evj, 0);
    const int nchunks = (E + ECHUNK - 1) / ECHUNK;
    edge_bal_kernel<<<(nchunks + 7) / 8, 256>>>(E);
    out_kernel<<<(V * 32 + 255) / 256, 256>>>(Wout, bout, out, V);
}